// round 1
// baseline (speedup 1.0000x reference)
#include <cuda_runtime.h>
#include <math.h>

#define NH 4
#define NN 1024
#define EE 4096
#define NLE 16384
#define FN 128
#define FE 64
#define FNO 128
#define FEO 64
#define NODE_OUT_SZ (NH*NN*FNO)   /* 524288 */

// ---------------- scratch (device globals; no runtime allocation) ----------------
__device__ float g_nq[NN*NH*FN];     // [1024,512] flat == [4,1024,128]
__device__ float g_nv[NN*NH*FN];
__device__ float g_nk[NN*NH];        // [1024,4] flat == [4,1024]
__device__ float g_eq[EE*NH*FE];     // [4096,256] flat == [4,4096,64]
__device__ float g_ev[EE*NH*FE];
__device__ float g_ek[EE*NH];        // [4096,4] flat == [4,4096]
__device__ float g_tn[NH*FN];
__device__ float g_te[NH*FE];
__device__ float g_nsa[NH*NN];
__device__ float g_esa[NH*EE];
__device__ int   g_cnt_n[NN], g_fc_n[NN], g_off_n[NN+1], g_lst_n[EE];
__device__ int   g_cnt_e[EE], g_fc_e[EE], g_off_e[EE+1], g_lst_e[NLE];
__device__ float g_ncWT[FNO*FN];
__device__ float g_ecWT[FEO*FE];

// ---------------- K1: zero counters/t, transpose output-linear weights ----------------
__global__ void init_kernel(const float* __restrict__ ncW, const float* __restrict__ ecW)
{
    int idx = blockIdx.x * blockDim.x + threadIdx.x;
    int stride = gridDim.x * blockDim.x;
    for (int i = idx; i < NN; i += stride)  { g_cnt_n[i] = 0; g_fc_n[i] = 0; }
    for (int i = idx; i < EE; i += stride)  { g_cnt_e[i] = 0; g_fc_e[i] = 0; }
    for (int i = idx; i < NH*FN; i += stride) g_tn[i] = 0.f;
    for (int i = idx; i < NH*FE; i += stride) g_te[i] = 0.f;
    for (int i = idx; i < FNO*FN; i += stride) {
        int o = i >> 7, f = i & 127;           // ncW [o][f]
        g_ncWT[f*FNO + o] = ncW[i];
    }
    for (int i = idx; i < FEO*FE; i += stride) {
        int o = i >> 6, f = i & 63;
        g_ecWT[f*FEO + o] = ecW[i];
    }
}

// ---------------- K2: tiled SGEMM  C[M,N] = A[M,K] @ W[N,K]^T + b ----------------
// BM=BN=64, BK=32, 256 threads, 4x4 microtile.
__global__ __launch_bounds__(256)
void gemm_bias_kernel(const float* __restrict__ A, const float* __restrict__ W,
                      const float* __restrict__ bias, float* __restrict__ C,
                      int M, int Nout, int K)
{
    __shared__ float As[32][64];
    __shared__ float Bs[32][64];
    int tid = threadIdx.x;
    int tx = tid & 15, ty = tid >> 4;
    int bm = blockIdx.y * 64, bn = blockIdx.x * 64;

    float acc[4][4];
#pragma unroll
    for (int i = 0; i < 4; i++)
#pragma unroll
        for (int j = 0; j < 4; j++) acc[i][j] = 0.f;

    for (int k0 = 0; k0 < K; k0 += 32) {
#pragma unroll
        for (int j = 0; j < 2; j++) {
            int f4 = tid + j * 256;          // 512 float4 per tile
            int m  = f4 >> 3;                // 0..63
            int k4 = f4 & 7;                 // 0..7
            float4 va = *reinterpret_cast<const float4*>(&A[(size_t)(bm + m) * K + k0 + k4 * 4]);
            As[k4*4+0][m] = va.x; As[k4*4+1][m] = va.y; As[k4*4+2][m] = va.z; As[k4*4+3][m] = va.w;
            float4 vb = *reinterpret_cast<const float4*>(&W[(size_t)(bn + m) * K + k0 + k4 * 4]);
            Bs[k4*4+0][m] = vb.x; Bs[k4*4+1][m] = vb.y; Bs[k4*4+2][m] = vb.z; Bs[k4*4+3][m] = vb.w;
        }
        __syncthreads();
#pragma unroll
        for (int kk = 0; kk < 32; kk++) {
            float4 a = *reinterpret_cast<const float4*>(&As[kk][ty * 4]);
            float4 b = *reinterpret_cast<const float4*>(&Bs[kk][tx * 4]);
            float ra[4] = {a.x, a.y, a.z, a.w};
            float rb[4] = {b.x, b.y, b.z, b.w};
#pragma unroll
            for (int i = 0; i < 4; i++)
#pragma unroll
                for (int j = 0; j < 4; j++) acc[i][j] += ra[i] * rb[j];
        }
        __syncthreads();
    }
#pragma unroll
    for (int i = 0; i < 4; i++) {
        int row = bm + ty * 4 + i;
        int col = bn + tx * 4;
        float4 r;
        r.x = acc[i][0] + bias[col+0];
        r.y = acc[i][1] + bias[col+1];
        r.z = acc[i][2] + bias[col+2];
        r.w = acc[i][3] + bias[col+3];
        *reinterpret_cast<float4*>(&C[(size_t)row * Nout + col]) = r;
    }
}

// ---------------- K3: small K-projections (nk, ek) + CSR degree counts ----------------
__global__ void proj_count_kernel(const float* __restrict__ node_in, const float* __restrict__ edge_in,
                                  const float* __restrict__ nkW, const float* __restrict__ nkb,
                                  const float* __restrict__ ekW, const float* __restrict__ ekb,
                                  const int* __restrict__ src, const int* __restrict__ lg_src)
{
    int idx = blockIdx.x * blockDim.x + threadIdx.x;
    if (idx < NN * NH) {
        int row = idx >> 2, c = idx & 3;
        const float* a = node_in + row * FN;
        const float* w = nkW + c * FN;
        float s = nkb[c];
        for (int k = 0; k < FN; k++) s += a[k] * w[k];
        g_nk[idx] = s;
    } else if (idx < NN*NH + EE*NH) {
        int j = idx - NN*NH;
        int row = j >> 2, c = j & 3;
        const float* a = edge_in + row * FE;
        const float* w = ekW + c * FE;
        float s = ekb[c];
        for (int k = 0; k < FE; k++) s += a[k] * w[k];
        g_ek[j] = s;
    } else if (idx < NN*NH + EE*NH + EE) {
        int e = idx - (NN*NH + EE*NH);
        atomicAdd(&g_cnt_n[src[e]], 1);
    } else if (idx < NN*NH + EE*NH + EE + NLE) {
        int l = idx - (NN*NH + EE*NH + EE);
        atomicAdd(&g_cnt_e[lg_src[l]], 1);
    }
}

// ---------------- K4: exclusive scan of degree counts -> row offsets ----------------
__device__ void scan_impl(const int* __restrict__ in, int* __restrict__ out, int items)
{
    __shared__ int sums[1024];
    int tid = threadIdx.x;
    int loc[4];
    int s = 0;
#pragma unroll
    for (int j = 0; j < 4; j++) {
        loc[j] = (j < items) ? in[tid * items + j] : 0;
        s += (j < items) ? loc[j] : 0;
    }
    sums[tid] = s;
    __syncthreads();
    for (int off = 1; off < 1024; off <<= 1) {
        int add = (tid >= off) ? sums[tid - off] : 0;
        __syncthreads();
        sums[tid] += add;
        __syncthreads();
    }
    int run = (tid == 0) ? 0 : sums[tid - 1];
    for (int j = 0; j < items; j++) {
        out[tid * items + j] = run;
        run += loc[j];
    }
    if (tid == 1023) out[1024 * items] = sums[1023];
}

__global__ __launch_bounds__(1024)
void scan_kernel()
{
    if (blockIdx.x == 0) scan_impl(g_cnt_n, g_off_n, 1);
    else                 scan_impl(g_cnt_e, g_off_e, 4);
}

// ---------------- K5: CSR fill ----------------
__global__ void fill_kernel(const int* __restrict__ src, const int* __restrict__ lg_src)
{
    int idx = blockIdx.x * blockDim.x + threadIdx.x;
    if (idx < EE) {
        int s = src[idx];
        int p = g_off_n[s] + atomicAdd(&g_fc_n[s], 1);
        g_lst_n[p] = idx;
    } else if (idx < EE + NLE) {
        int l = idx - EE;
        int s = lg_src[l];
        int p = g_off_e[s] + atomicAdd(&g_fc_e[s], 1);
        g_lst_e[p] = l;
    }
}

// ---------------- K6: t[h,f] = sum_m Q[h,m,f]*K[h,m] ----------------
__global__ __launch_bounds__(128)
void tvec_kernel()
{
    int bid = blockIdx.x, tid = threadIdx.x;
    if (bid < 32) {                      // node: h in 0..3, 8 chunks of 128 rows
        int h = bid >> 3, chunk = bid & 7;
        const float* q = g_nq + h * (NN*FN);
        const float* k = g_nk + h * NN;
        float acc = 0.f;
        int m0 = chunk * 128;
        for (int m = m0; m < m0 + 128; m++) acc += q[m * FN + tid] * k[m];
        atomicAdd(&g_tn[h * FN + tid], acc);
    } else {                             // edge: h in 0..3, 8 chunks of 512 rows, 64 active lanes
        int eb = bid - 32;
        int h = eb >> 3, chunk = eb & 7;
        if (tid < FE) {
            const float* q = g_eq + h * (EE*FE);
            const float* k = g_ek + h * EE;
            float acc = 0.f;
            int m0 = chunk * 512;
            for (int m = m0; m < m0 + 512; m++) acc += q[m * FE + tid] * k[m];
            atomicAdd(&g_te[h * FE + tid], acc);
        }
    }
}

// ---------------- K7: s = Q @ t, softmax over rows (per head) ----------------
__global__ __launch_bounds__(1024)
void softmax_kernel()
{
    __shared__ float s[4096];
    __shared__ float red[33];
    int bid = blockIdx.x, tid = threadIdx.x;
    int warp = tid >> 5, lane = tid & 31;
    const float* q; const float* t; float* out; int M;
    bool isNode = (bid < 4);
    if (isNode) { int h = bid;     q = g_nq + h*(NN*FN); t = g_tn + h*FN; out = g_nsa + h*NN; M = NN; }
    else        { int h = bid - 4; q = g_eq + h*(EE*FE); t = g_te + h*FE; out = g_esa + h*EE; M = EE; }

    if (isNode) {
        float4 tv = *reinterpret_cast<const float4*>(&t[lane * 4]);
        for (int r = warp; r < M; r += 32) {
            float4 qv = *reinterpret_cast<const float4*>(&q[r * FN + lane * 4]);
            float d = qv.x*tv.x + qv.y*tv.y + qv.z*tv.z + qv.w*tv.w;
#pragma unroll
            for (int o = 16; o; o >>= 1) d += __shfl_xor_sync(0xffffffffu, d, o);
            if (lane == 0) s[r] = d;
        }
    } else {
        float2 tv = *reinterpret_cast<const float2*>(&t[lane * 2]);
        for (int r = warp; r < M; r += 32) {
            float2 qv = *reinterpret_cast<const float2*>(&q[r * FE + lane * 2]);
            float d = qv.x*tv.x + qv.y*tv.y;
#pragma unroll
            for (int o = 16; o; o >>= 1) d += __shfl_xor_sync(0xffffffffu, d, o);
            if (lane == 0) s[r] = d;
        }
    }
    __syncthreads();

    // block max
    float m = -1e30f;
    for (int r = tid; r < M; r += 1024) m = fmaxf(m, s[r]);
#pragma unroll
    for (int o = 16; o; o >>= 1) m = fmaxf(m, __shfl_xor_sync(0xffffffffu, m, o));
    if (lane == 0) red[warp] = m;
    __syncthreads();
    if (tid == 0) {
        float v = red[0];
        for (int w = 1; w < 32; w++) v = fmaxf(v, red[w]);
        red[32] = v;
    }
    __syncthreads();
    float mx = red[32];

    // exp + block sum
    float sum = 0.f;
    for (int r = tid; r < M; r += 1024) {
        float e = expf(s[r] - mx);
        s[r] = e;
        sum += e;
    }
#pragma unroll
    for (int o = 16; o; o >>= 1) sum += __shfl_xor_sync(0xffffffffu, sum, o);
    __syncthreads();            // protect red[] reuse
    if (lane == 0) red[warp] = sum;
    __syncthreads();
    if (tid == 0) {
        float v = 0.f;
        for (int w = 0; w < 32; w++) v += red[w];
        red[32] = v;
    }
    __syncthreads();
    float inv = 1.f / red[32];
    for (int r = tid; r < M; r += 1024) out[r] = s[r] * inv;
}

// ---------------- K8: node aggregation (dedup, last-wins) + output linear + relu ----------------
__global__ __launch_bounds__(128)
void node_out_kernel(const int* __restrict__ dst, const float* __restrict__ ncb,
                     float* __restrict__ out)
{
    int i = blockIdx.x, h = blockIdx.y, tid = threadIdx.x;
    int s0 = g_off_n[i], s1 = g_off_n[i + 1];
    float acc = 0.f;
    for (int p = s0; p < s1; p++) {
        int e = g_lst_n[p];
        int d = dst[e];
        bool win = true;
        for (int p2 = s0; p2 < s1; p2++) {
            int e2 = g_lst_n[p2];
            if (e2 > e && dst[e2] == d) win = false;   // last write wins
        }
        if (win) {
            float val = g_esa[h * EE + e];
            acc += val * g_nv[h * (NN*FN) + d * FN + tid];
        }
    }
    __shared__ float agg[FN];
    agg[tid] = acc;
    __syncthreads();
    float r = ncb[tid];
#pragma unroll 4
    for (int f = 0; f < FN; f++) r += agg[f] * g_ncWT[f * FNO + tid];
    out[h * (NN*FNO) + i * FNO + tid] = fmaxf(r, 0.f);
}

// ---------------- K9: edge aggregation (unique lg_dst) + output linear + relu ----------------
__global__ __launch_bounds__(64)
void edge_out_kernel(const int* __restrict__ dst, const int* __restrict__ lg_dst,
                     const float* __restrict__ ecb, float* __restrict__ out)
{
    int i = blockIdx.x, h = blockIdx.y, tid = threadIdx.x;
    int s0 = g_off_e[i], s1 = g_off_e[i + 1];
    float acc = 0.f;
    for (int p = s0; p < s1; p++) {
        int l = g_lst_e[p];
        int ld = lg_dst[l];
        bool win = true;
        for (int p2 = s0; p2 < s1; p2++) {
            int l2 = g_lst_e[p2];
            if (l2 > l && lg_dst[l2] == ld) win = false;  // single representative per unique lg_dst
        }
        if (win) acc += g_ev[h * (EE*FE) + ld * FE + tid];
    }
    acc *= g_nsa[h * NN + dst[i]];
    __shared__ float agg[FE];
    agg[tid] = acc;
    __syncthreads();
    float r = ecb[tid];
#pragma unroll 4
    for (int f = 0; f < FE; f++) r += agg[f] * g_ecWT[f * FEO + tid];
    out[NODE_OUT_SZ + h * (EE*FEO) + i * FEO + tid] = fmaxf(r, 0.f);
}

// ---------------- launcher ----------------
extern "C" void kernel_launch(void* const* d_in, const int* in_sizes, int n_in,
                              void* d_out, int out_size)
{
    const float* node_inputs = (const float*)d_in[0];
    const float* edge_inputs = (const float*)d_in[1];
    const int*   src         = (const int*)d_in[2];
    const int*   dst         = (const int*)d_in[3];
    const int*   lg_src      = (const int*)d_in[4];
    const int*   lg_dst      = (const int*)d_in[5];
    const float* nqW = (const float*)d_in[6];
    const float* nqb = (const float*)d_in[7];
    const float* nkW = (const float*)d_in[8];
    const float* nkb = (const float*)d_in[9];
    const float* nvW = (const float*)d_in[10];
    const float* nvb = (const float*)d_in[11];
    const float* eqW = (const float*)d_in[12];
    const float* eqb = (const float*)d_in[13];
    const float* ekW = (const float*)d_in[14];
    const float* ekb = (const float*)d_in[15];
    const float* evW = (const float*)d_in[16];
    const float* evb = (const float*)d_in[17];
    const float* ncW = (const float*)d_in[18];
    const float* ncb = (const float*)d_in[19];
    const float* ecW = (const float*)d_in[20];
    const float* ecb = (const float*)d_in[21];
    float* out = (float*)d_out;

    float* p_nq; cudaGetSymbolAddress((void**)&p_nq, g_nq);
    float* p_nv; cudaGetSymbolAddress((void**)&p_nv, g_nv);
    float* p_eq; cudaGetSymbolAddress((void**)&p_eq, g_eq);
    float* p_ev; cudaGetSymbolAddress((void**)&p_ev, g_ev);

    // K1: init
    init_kernel<<<64, 256>>>(ncW, ecW);

    // K2: projections (Q/V for nodes+edges)
    gemm_bias_kernel<<<dim3(8, 16), 256>>>(node_inputs, nqW, nqb, p_nq, NN, NH*FN, FN);
    gemm_bias_kernel<<<dim3(8, 16), 256>>>(node_inputs, nvW, nvb, p_nv, NN, NH*FN, FN);
    gemm_bias_kernel<<<dim3(4, 64), 256>>>(edge_inputs, eqW, eqb, p_eq, EE, NH*FE, FE);
    gemm_bias_kernel<<<dim3(4, 64), 256>>>(edge_inputs, evW, evb, p_ev, EE, NH*FE, FE);

    // K3: nk/ek projections + CSR counts  (total threads = 4096+16384+4096+16384 = 40960)
    proj_count_kernel<<<160, 256>>>(node_inputs, edge_inputs, nkW, nkb, ekW, ekb, src, lg_src);

    // K4: offsets
    scan_kernel<<<2, 1024>>>();

    // K5: CSR fill  (4096 + 16384 = 20480 threads)
    fill_kernel<<<80, 256>>>(src, lg_src);

    // K6: t vectors
    tvec_kernel<<<64, 128>>>();

    // K7: scores + softmax (4 node heads + 4 edge heads)
    softmax_kernel<<<8, 1024>>>();

    // K8: node outputs
    node_out_kernel<<<dim3(NN, NH), 128>>>(dst, ncb, out);

    // K9: edge outputs
    edge_out_kernel<<<dim3(EE, NH), 64>>>(dst, lg_dst, ecb, out);
}

// round 2
// speedup vs baseline: 1.2583x; 1.2583x over previous
#include <cuda_runtime.h>
#include <math.h>

#define NH 4
#define NN 1024
#define EE 4096
#define NLE 16384
#define FN 128
#define FE 64
#define FNO 128
#define FEO 64
#define NODE_OUT_SZ (NH*NN*FNO)   /* 524288 */

// ---------------- scratch (device globals; zero-initialized at load) ----------------
__device__ float g_nq[NN*NH*FN];
__device__ float g_nv[NN*NH*FN];
__device__ float g_nk[NN*NH];
__device__ float g_eq[EE*NH*FE];
__device__ float g_ev[EE*NH*FE];
__device__ float g_ek[EE*NH];
__device__ float g_tn[NH*FN];          // zeroed at end of each run
__device__ float g_te[NH*FE];          // zeroed at end of each run
__device__ float g_nsa[NH*NN];
__device__ float g_esa[NH*EE];
__device__ int   g_cnt_n[NN], g_fc_n[NN], g_off_n[NN+1], g_lst_n[EE];
__device__ int   g_cnt_e[EE], g_fc_e[EE], g_off_e[EE+1], g_lst_e[NLE];
__device__ float g_ncWT[FNO*FN];
__device__ float g_ecWT[FEO*FE];

// ---------------- K1: prep — nk/ek projections, CSR degree counts, weight transposes ----------------
// 240 blocks x 256 threads = 61440 threads.
// Requires g_cnt_* zeroed on entry (true at load; re-zeroed by out_kernel each run).
__global__ __launch_bounds__(256)
void prep_kernel(const float* __restrict__ node_in, const float* __restrict__ edge_in,
                 const float* __restrict__ nkW, const float* __restrict__ nkb,
                 const float* __restrict__ ekW, const float* __restrict__ ekb,
                 const int* __restrict__ src, const int* __restrict__ lg_src,
                 const float* __restrict__ ncW, const float* __restrict__ ecW)
{
    int idx = blockIdx.x * blockDim.x + threadIdx.x;
    if (idx < NN*NH) {                                   // nk projection
        int row = idx >> 2, c = idx & 3;
        const float* a = node_in + row * FN;
        const float* w = nkW + c * FN;
        float s = nkb[c];
        for (int k = 0; k < FN; k++) s += a[k] * w[k];
        g_nk[idx] = s;
    } else if (idx < NN*NH + EE*NH) {                    // ek projection
        int j = idx - NN*NH;
        int row = j >> 2, c = j & 3;
        const float* a = edge_in + row * FE;
        const float* w = ekW + c * FE;
        float s = ekb[c];
        for (int k = 0; k < FE; k++) s += a[k] * w[k];
        g_ek[j] = s;
    } else if (idx < NN*NH + EE*NH + EE) {               // node CSR degree
        int e = idx - (NN*NH + EE*NH);
        atomicAdd(&g_cnt_n[src[e]], 1);
    } else if (idx < NN*NH + EE*NH + EE + NLE) {         // edge CSR degree
        int l = idx - (NN*NH + EE*NH + EE);
        atomicAdd(&g_cnt_e[lg_src[l]], 1);
    } else if (idx < NN*NH + EE*NH + EE + NLE + FNO*FN) { // ncW transpose
        int i = idx - (NN*NH + EE*NH + EE + NLE);
        int o = i >> 7, f = i & 127;
        g_ncWT[f*FNO + o] = ncW[i];
    } else if (idx < NN*NH + EE*NH + EE + NLE + FNO*FN + FEO*FE) { // ecW transpose
        int i = idx - (NN*NH + EE*NH + EE + NLE + FNO*FN);
        int o = i >> 6, f = i & 63;
        g_ecWT[f*FEO + o] = ecW[i];
    }
}

// ---------------- K2: merged tiled SGEMMs  C[M,N] = A[M,K] @ W[N,K]^T + b ----------------
__device__ __forceinline__
void gemm_tile(const float* __restrict__ A, const float* __restrict__ W,
               const float* __restrict__ bias, float* __restrict__ C,
               int bm, int bn, int Nout, int K)
{
    __shared__ float As[32][64];
    __shared__ float Bs[32][64];
    int tid = threadIdx.x;
    int tx = tid & 15, ty = tid >> 4;

    float acc[4][4];
#pragma unroll
    for (int i = 0; i < 4; i++)
#pragma unroll
        for (int j = 0; j < 4; j++) acc[i][j] = 0.f;

    for (int k0 = 0; k0 < K; k0 += 32) {
#pragma unroll
        for (int j = 0; j < 2; j++) {
            int f4 = tid + j * 256;
            int m  = f4 >> 3;
            int k4 = f4 & 7;
            float4 va = *reinterpret_cast<const float4*>(&A[(size_t)(bm + m) * K + k0 + k4 * 4]);
            As[k4*4+0][m] = va.x; As[k4*4+1][m] = va.y; As[k4*4+2][m] = va.z; As[k4*4+3][m] = va.w;
            float4 vb = *reinterpret_cast<const float4*>(&W[(size_t)(bn + m) * K + k0 + k4 * 4]);
            Bs[k4*4+0][m] = vb.x; Bs[k4*4+1][m] = vb.y; Bs[k4*4+2][m] = vb.z; Bs[k4*4+3][m] = vb.w;
        }
        __syncthreads();
#pragma unroll
        for (int kk = 0; kk < 32; kk++) {
            float4 a = *reinterpret_cast<const float4*>(&As[kk][ty * 4]);
            float4 b = *reinterpret_cast<const float4*>(&Bs[kk][tx * 4]);
            float ra[4] = {a.x, a.y, a.z, a.w};
            float rb[4] = {b.x, b.y, b.z, b.w};
#pragma unroll
            for (int i = 0; i < 4; i++)
#pragma unroll
                for (int j = 0; j < 4; j++) acc[i][j] += ra[i] * rb[j];
        }
        __syncthreads();
    }
#pragma unroll
    for (int i = 0; i < 4; i++) {
        int row = bm + ty * 4 + i;
        int col = bn + tx * 4;
        float4 r;
        r.x = acc[i][0] + bias[col+0];
        r.y = acc[i][1] + bias[col+1];
        r.z = acc[i][2] + bias[col+2];
        r.w = acc[i][3] + bias[col+3];
        *reinterpret_cast<float4*>(&C[(size_t)row * Nout + col]) = r;
    }
}

__global__ __launch_bounds__(256)
void gemms_kernel(const float* __restrict__ nin, const float* __restrict__ ein,
                  const float* __restrict__ nqW, const float* __restrict__ nqb,
                  const float* __restrict__ nvW, const float* __restrict__ nvb,
                  const float* __restrict__ eqW, const float* __restrict__ eqb,
                  const float* __restrict__ evW, const float* __restrict__ evb)
{
    int b = blockIdx.x;
    if (b < 128) {
        gemm_tile(nin, nqW, nqb, g_nq, (b >> 3) * 64, (b & 7) * 64, NH*FN, FN);
    } else if (b < 256) {
        b -= 128;
        gemm_tile(nin, nvW, nvb, g_nv, (b >> 3) * 64, (b & 7) * 64, NH*FN, FN);
    } else if (b < 512) {
        b -= 256;
        gemm_tile(ein, eqW, eqb, g_eq, (b >> 2) * 64, (b & 3) * 64, NH*FE, FE);
    } else {
        b -= 512;
        gemm_tile(ein, evW, evb, g_ev, (b >> 2) * 64, (b & 3) * 64, NH*FE, FE);
    }
}

// ---------------- K3: exclusive scan of degree counts -> row offsets ----------------
__device__ void scan_impl(const int* __restrict__ in, int* __restrict__ out, int items)
{
    __shared__ int sums[1024];
    int tid = threadIdx.x;
    int loc[4];
    int s = 0;
#pragma unroll
    for (int j = 0; j < 4; j++) {
        loc[j] = (j < items) ? in[tid * items + j] : 0;
        s += (j < items) ? loc[j] : 0;
    }
    sums[tid] = s;
    __syncthreads();
    for (int off = 1; off < 1024; off <<= 1) {
        int add = (tid >= off) ? sums[tid - off] : 0;
        __syncthreads();
        sums[tid] += add;
        __syncthreads();
    }
    int run = (tid == 0) ? 0 : sums[tid - 1];
    for (int j = 0; j < items; j++) {
        out[tid * items + j] = run;
        run += loc[j];
    }
    if (tid == 1023) out[1024 * items] = sums[1023];
}

__global__ __launch_bounds__(1024)
void scan_kernel()
{
    if (blockIdx.x == 0) scan_impl(g_cnt_n, g_off_n, 1);
    else                 scan_impl(g_cnt_e, g_off_e, 4);
}

// ---------------- K4: CSR fill + t-vector reduction (independent; merged) ----------------
// grid 144 x 256: blocks [0,80) fill, [80,112) node tvec, [112,144) edge tvec
__global__ __launch_bounds__(256)
void fill_tvec_kernel(const int* __restrict__ src, const int* __restrict__ lg_src)
{
    int bid = blockIdx.x, tid = threadIdx.x;
    if (bid < 80) {
        int idx = bid * 256 + tid;
        if (idx < EE) {
            int s = src[idx];
            int p = g_off_n[s] + atomicAdd(&g_fc_n[s], 1);
            g_lst_n[p] = idx;
        } else if (idx < EE + NLE) {
            int l = idx - EE;
            int s = lg_src[l];
            int p = g_off_e[s] + atomicAdd(&g_fc_e[s], 1);
            g_lst_e[p] = l;
        }
    } else if (bid < 112) {
        int b = bid - 80;                 // 0..31: node tvec, h=b>>3, chunk=b&7 (128 rows)
        if (tid < FN) {
            int h = b >> 3, chunk = b & 7;
            const float* q = g_nq + h * (NN*FN);
            const float* k = g_nk + h * NN;
            float acc = 0.f;
            int m0 = chunk * 128;
            for (int m = m0; m < m0 + 128; m++) acc += q[m * FN + tid] * k[m];
            atomicAdd(&g_tn[h * FN + tid], acc);
        }
    } else {
        int b = bid - 112;                // 0..31: edge tvec, h=b>>3, chunk=b&7 (512 rows)
        if (tid < FE) {
            int h = b >> 3, chunk = b & 7;
            const float* q = g_eq + h * (EE*FE);
            const float* k = g_ek + h * EE;
            float acc = 0.f;
            int m0 = chunk * 512;
            for (int m = m0; m < m0 + 512; m++) acc += q[m * FE + tid] * k[m];
            atomicAdd(&g_te[h * FE + tid], acc);
        }
    }
}

// ---------------- K5: raw scores s = Q @ t (one warp per row) ----------------
// warps: node NH*NN = 4096, edge NH*EE = 16384 -> 20480 warps, 2560 blocks x 256
__global__ __launch_bounds__(256)
void scores_kernel()
{
    int w = blockIdx.x * 8 + (threadIdx.x >> 5);
    int lane = threadIdx.x & 31;
    if (w < NH*NN) {
        int h = w >> 10, r = w & (NN - 1);
        float4 tv = *reinterpret_cast<const float4*>(&g_tn[h*FN + lane*4]);
        float4 qv = *reinterpret_cast<const float4*>(&g_nq[h*(NN*FN) + r*FN + lane*4]);
        float d = qv.x*tv.x + qv.y*tv.y + qv.z*tv.z + qv.w*tv.w;
#pragma unroll
        for (int o = 16; o; o >>= 1) d += __shfl_xor_sync(0xffffffffu, d, o);
        if (lane == 0) g_nsa[h*NN + r] = d;
    } else {
        int w2 = w - NH*NN;
        int h = w2 >> 12, r = w2 & (EE - 1);
        float2 tv = *reinterpret_cast<const float2*>(&g_te[h*FE + lane*2]);
        float2 qv = *reinterpret_cast<const float2*>(&g_eq[h*(EE*FE) + r*FE + lane*2]);
        float d = qv.x*tv.x + qv.y*tv.y;
#pragma unroll
        for (int o = 16; o; o >>= 1) d += __shfl_xor_sync(0xffffffffu, d, o);
        if (lane == 0) g_esa[h*EE + r] = d;
    }
}

// ---------------- K6: per-head softmax normalize (in place) ----------------
__global__ __launch_bounds__(1024)
void softmax_kernel()
{
    __shared__ float red[32];
    __shared__ float bc_max, bc_sum;
    int bid = blockIdx.x, tid = threadIdx.x;
    int warp = tid >> 5, lane = tid & 31;
    float* buf; int cnt;
    if (bid < 4) { buf = g_nsa + bid * NN;       cnt = 1; }
    else         { buf = g_esa + (bid - 4) * EE; cnt = 4; }

    float v[4];
    float m = -1e30f;
    for (int j = 0; j < cnt; j++) { v[j] = buf[tid + j*1024]; m = fmaxf(m, v[j]); }
#pragma unroll
    for (int o = 16; o; o >>= 1) m = fmaxf(m, __shfl_xor_sync(0xffffffffu, m, o));
    if (lane == 0) red[warp] = m;
    __syncthreads();
    if (tid == 0) {
        float x = red[0];
        for (int w = 1; w < 32; w++) x = fmaxf(x, red[w]);
        bc_max = x;
    }
    __syncthreads();
    float mx = bc_max;

    float sum = 0.f;
    for (int j = 0; j < cnt; j++) { v[j] = expf(v[j] - mx); sum += v[j]; }
#pragma unroll
    for (int o = 16; o; o >>= 1) sum += __shfl_xor_sync(0xffffffffu, sum, o);
    __syncthreads();
    if (lane == 0) red[warp] = sum;
    __syncthreads();
    if (tid == 0) {
        float x = 0.f;
        for (int w = 0; w < 32; w++) x += red[w];
        bc_sum = x;
    }
    __syncthreads();
    float inv = 1.f / bc_sum;
    for (int j = 0; j < cnt; j++) buf[tid + j*1024] = v[j] * inv;
}

// ---------------- K7: merged outputs (node agg+linear, edge agg+linear, counter reset) ----------------
// grid 2064 x 128: [0,1024) node (4 rows/blk), [1024,2048) edge (16 rows/blk), [2048,2064) cleanup
__global__ __launch_bounds__(128)
void out_kernel(const int* __restrict__ dst, const int* __restrict__ lg_dst,
                const float* __restrict__ ncb, const float* __restrict__ ecb,
                float* __restrict__ out)
{
    int bid = blockIdx.x, tid = threadIdx.x;
    if (bid < 1024) {
        // ---- node: pairs (h,i) = bid*4 .. bid*4+3 ----
        __shared__ float agg[4][FN];
        int h = bid >> 8;
        int i0 = (bid & 255) * 4;
#pragma unroll
        for (int r = 0; r < 4; r++) {
            int i = i0 + r;
            int s0 = g_off_n[i], s1 = g_off_n[i + 1];
            float acc = 0.f;
            for (int p = s0; p < s1; p++) {
                int e = g_lst_n[p];
                int d = dst[e];
                bool win = true;
                for (int p2 = s0; p2 < s1; p2++) {
                    int e2 = g_lst_n[p2];
                    if (e2 > e && dst[e2] == d) win = false;   // last write wins
                }
                if (win) acc += g_esa[h*EE + e] * g_nv[h*(NN*FN) + d*FN + tid];
            }
            agg[r][tid] = acc;
        }
        __syncthreads();
        float b = ncb[tid];
        float a0 = b, a1 = b, a2 = b, a3 = b;
#pragma unroll 4
        for (int f = 0; f < FN; f++) {
            float w = g_ncWT[f*FNO + tid];
            a0 += agg[0][f] * w;
            a1 += agg[1][f] * w;
            a2 += agg[2][f] * w;
            a3 += agg[3][f] * w;
        }
        float* o = out + h*(NN*FNO) + i0*FNO + tid;
        o[0*FNO] = fmaxf(a0, 0.f);
        o[1*FNO] = fmaxf(a1, 0.f);
        o[2*FNO] = fmaxf(a2, 0.f);
        o[3*FNO] = fmaxf(a3, 0.f);
    } else if (bid < 2048) {
        // ---- edge: pairs (h,i) = b*16 .. b*16+15, two half-blocks of 8 rows ----
        __shared__ float agg[16][FEO];
        int b = bid - 1024;
        int h = b >> 8;
        int i0 = (b & 255) * 16;
        int col = tid & 63, rg = tid >> 6;
#pragma unroll
        for (int k = 0; k < 8; k++) {
            int lr = rg * 8 + k;
            int i = i0 + lr;
            int s0 = g_off_e[i], s1 = g_off_e[i + 1];
            float acc = 0.f;
            for (int p = s0; p < s1; p++) {
                int l = g_lst_e[p];
                int ld = lg_dst[l];
                bool win = true;
                for (int p2 = s0; p2 < s1; p2++) {
                    int l2 = g_lst_e[p2];
                    if (l2 > l && lg_dst[l2] == ld) win = false;
                }
                if (win) acc += g_ev[h*(EE*FE) + ld*FE + col];
            }
            acc *= g_nsa[h*NN + dst[i]];
            agg[lr][col] = acc;
        }
        __syncthreads();
        float a[8];
        float bb = ecb[col];
#pragma unroll
        for (int k = 0; k < 8; k++) a[k] = bb;
#pragma unroll 4
        for (int f = 0; f < FE; f++) {
            float w = g_ecWT[f*FEO + col];
#pragma unroll
            for (int k = 0; k < 8; k++) a[k] += agg[rg*8 + k][f] * w;
        }
#pragma unroll
        for (int k = 0; k < 8; k++) {
            int i = i0 + rg*8 + k;
            out[NODE_OUT_SZ + h*(EE*FEO) + i*FEO + col] = fmaxf(a[k], 0.f);
        }
    } else {
        // ---- cleanup: reset counters/accumulators for next run ----
        int idx = (bid - 2048) * 128 + tid;       // 0..2047
        for (int i = idx; i < NN; i += 2048) { g_cnt_n[i] = 0; g_fc_n[i] = 0; }
        for (int i = idx; i < EE; i += 2048) { g_cnt_e[i] = 0; g_fc_e[i] = 0; }
        for (int i = idx; i < NH*FN; i += 2048) g_tn[i] = 0.f;
        for (int i = idx; i < NH*FE; i += 2048) g_te[i] = 0.f;
    }
}

// ---------------- launcher ----------------
extern "C" void kernel_launch(void* const* d_in, const int* in_sizes, int n_in,
                              void* d_out, int out_size)
{
    const float* node_inputs = (const float*)d_in[0];
    const float* edge_inputs = (const float*)d_in[1];
    const int*   src         = (const int*)d_in[2];
    const int*   dst         = (const int*)d_in[3];
    const int*   lg_src      = (const int*)d_in[4];
    const int*   lg_dst      = (const int*)d_in[5];
    const float* nqW = (const float*)d_in[6];
    const float* nqb = (const float*)d_in[7];
    const float* nkW = (const float*)d_in[8];
    const float* nkb = (const float*)d_in[9];
    const float* nvW = (const float*)d_in[10];
    const float* nvb = (const float*)d_in[11];
    const float* eqW = (const float*)d_in[12];
    const float* eqb = (const float*)d_in[13];
    const float* ekW = (const float*)d_in[14];
    const float* ekb = (const float*)d_in[15];
    const float* evW = (const float*)d_in[16];
    const float* evb = (const float*)d_in[17];
    const float* ncW = (const float*)d_in[18];
    const float* ncb = (const float*)d_in[19];
    const float* ecW = (const float*)d_in[20];
    const float* ecb = (const float*)d_in[21];
    float* out = (float*)d_out;

    prep_kernel<<<240, 256>>>(node_inputs, edge_inputs, nkW, nkb, ekW, ekb,
                              src, lg_src, ncW, ecW);
    gemms_kernel<<<768, 256>>>(node_inputs, edge_inputs,
                               nqW, nqb, nvW, nvb, eqW, eqb, evW, evb);
    scan_kernel<<<2, 1024>>>();
    fill_tvec_kernel<<<144, 256>>>(src, lg_src);
    scores_kernel<<<2560, 256>>>();
    softmax_kernel<<<8, 1024>>>();
    out_kernel<<<2064, 128>>>(dst, lg_dst, ncb, ecb, out);
}